// round 2
// baseline (speedup 1.0000x reference)
#include <cuda_runtime.h>
#include <math.h>

#define TT 1460
#define GG 5000
#define TS 60           // timesteps per smem tile
#define NT 25           // ceil(1460/60)
#define ROWF 96         // 32 cells * 3 floats per timestep row

__device__ __forceinline__ void cp_async16(void* sm, const void* gm) {
    unsigned a = (unsigned)__cvta_generic_to_shared(sm);
    asm volatile("cp.async.cg.shared.global [%0], [%1], 16;\n" :: "r"(a), "l"(gm));
}
__device__ __forceinline__ void cp_commit() { asm volatile("cp.async.commit_group;\n" ::: "memory"); }
__device__ __forceinline__ void cp_wait1()  { asm volatile("cp.async.wait_group 1;\n" ::: "memory"); }
__device__ __forceinline__ void cp_wait0()  { asm volatile("cp.async.wait_group 0;\n" ::: "memory"); }

__global__ __launch_bounds__(32, 1)
void hmets_kernel(const float* __restrict__ x,
                  const float* __restrict__ par,
                  float* __restrict__ out)
{
    __shared__ float sm[2 * TS * ROWF];   // 46080 B, double buffered
    const int lane = threadIdx.x;
    const int g0   = blockIdx.x * 32;
    const int g    = g0 + lane;
    const bool active  = (g < GG);
    const bool fullblk = (g0 + 32 <= GG);

    // ---------------- parameters: only the last timestep row is live ----------------
    const float* pr = par + ((size_t)(TT - 1) * GG + (active ? g : (GG - 1))) * 20;
    float s[20];
#pragma unroll
    for (int i = 0; i < 20; i++) {
        float v = __ldg(pr + i);
        s[i] = 1.0f / (1.0f + expf(-v));
    }
    const float ddf_min = 20.0f * s[0];
    const float ddf_sum = ddf_min + 20.0f * s[1];          // ddf_min + ddf_plus
    const float Tbm     = -2.0f + 5.0f * s[2];
    const float Kcum    = 0.01f + 0.19f * s[3];
    const float fcmin   = 0.1f * s[4];
    const float fc_sum  = fcmin + 0.01f + 0.24f * s[5];    // fcmin + fcmin_plus
    const float Ccum    = 0.005f + 0.045f * s[6];
    const float Tbf     = -5.0f + 7.0f * s[7];
    const float Kf      = 5.0f * s[8];
    const float efe     = s[9];
    const float ETe     = 3.0f * s[10];
    const float cRun    = s[11];
    const float cV2P    = 1e-5f + (0.02f - 1e-5f) * s[12];
    const float cVad    = 0.1f * s[13];
    const float cPh     = 1e-5f + (0.01f - 1e-5f) * s[14];
    const float Vmax    = 0.001f + (500.0f - 0.001f) * s[15];
    const float invVmax = 1.0f / Vmax;

    // ---------------- gamma unit hydrographs (15 taps each, normalized) -------------
    float uh1[15], uh2[15];
    {
        float a1 = 0.3f  + (20.0f - 0.3f)  * s[16];
        float b1 = 0.01f + (5.0f  - 0.01f) * s[17];
        float a2 = 0.5f  + (13.0f - 0.5f)  * s[18];
        float b2 = 0.15f + (1.5f  - 0.15f) * s[19];
        float i1 = 1.0f / b1, i2 = 1.0f / b2;
        float n1 = 0.f, n2 = 0.f;
#pragma unroll
        for (int l = 0; l < 15; l++) {
            float t  = (float)l + 0.5f;
            float w1 = powf(t, a1 - 1.0f) * expf(-t * i1);
            float w2 = powf(t, a2 - 1.0f) * expf(-t * i2);
            uh1[l] = w1; uh2[l] = w2;
            n1 += w1; n2 += w2;
        }
        n1 = 1.0f / n1; n2 = 1.0f / n2;
#pragma unroll
        for (int l = 0; l < 15; l++) { uh1[l] *= n1; uh2[l] *= n2; }
    }

    // ---------------- tile prefetch (cp.async for full blocks) ----------------------
    auto prefetch = [&](int k) {
        float* dst = sm + (k & 1) * (TS * ROWF);
        int t0  = k * TS;
        int len = min(TS, TT - t0);
        if (fullblk) {
            int n4 = len * 24;                       // 24 float4 per row
            for (int j = lane; j < n4; j += 32) {
                int row = j / 24, c = j - row * 24;
                const float* gp = x + (size_t)(t0 + row) * (GG * 3) + g0 * 3 + c * 4;
                cp_async16(dst + row * ROWF + c * 4, gp);
            }
        } else {                                     // tail block: guarded scalar loads
            int n = len * ROWF;
            for (int j = lane; j < n; j += 32) {
                int row = j / ROWF, c = j - row * ROWF;
                int cell = g0 + c / 3;
                float v = (cell < GG) ? __ldg(x + (size_t)(t0 + row) * (GG * 3) + g0 * 3 + c)
                                      : 0.0f;
                dst[row * ROWF + c] = v;
            }
        }
        cp_commit();
    };

    // ---------------- state + conv history ------------------------------------------
    float S = 1e-5f, W = 1e-5f, C = 1e-5f, P = 1e-5f;
    float V = 0.5f * Vmax;
    float hs[15], hd[15];
#pragma unroll
    for (int l = 0; l < 15; l++) { hs[l] = 0.f; hd[l] = 0.f; }

    prefetch(0);
    for (int k = 0; k < NT; k++) {
        int t0  = k * TS;
        int len = min(TS, TT - t0);
        if (k + 1 < NT) { prefetch(k + 1); cp_wait1(); }
        else            { cp_wait0(); }
        __syncwarp();
        const float* sb = sm + (k & 1) * (TS * ROWF);

        for (int i = 0; i < len; i++) {
            float Pp = sb[i * ROWF + lane * 3 + 0];
            float Tt = sb[i * ROWF + lane * 3 + 1];
            float PE = sb[i * ROWF + lane * 3 + 2];

            float rain = (Tt >= 0.0f) ? Pp : 0.0f;
            float snow = Pp - rain;

            // refreeze (pow kept off the state dependency chain)
            float base   = fmaxf(Tbf - Tt, 1e-5f);
            float pot_fr = Kf * exp2f(efe * __log2f(base));
            float fr     = fminf(pot_fr, W);
            W -= fr;
            S += fr;

            // melt
            float ddf  = fminf(ddf_sum, ddf_min * fmaf(Kcum, C, 1.0f));
            float melt = fminf(fmaxf(ddf * (Tt - Tbm), 0.0f), S + snow);
            S = S + snow - melt;
            C = (S > 1e-5f) ? (C + melt) : 0.0f;

            // water retention
            float wrf  = fmaxf(fc_sum * fmaf(-Ccum, C, 1.0f), fcmin);
            float wr   = wrf * S;
            float wtmp = W + melt + rain;
            float wa   = fmaxf(wtmp - wr, 0.0f);
            W = (wa > 0.0f) ? wr : wtmp;

            // vadose / phreatic
            float RET   = ETe * PE;
            float ratio = V * invVmax;
            float ht0   = cRun * ratio * wa;
            float infil = fmaxf(wa - ht0 - RET, 0.0f);
            float ht1   = cRun * ratio * ratio * infil;
            float ht2   = cVad * V;
            float v2p   = cV2P * V;
            V = V + infil - ht1 - ht2 - v2p;
            float over = fmaxf(V - Vmax, 0.0f);
            V -= over;
            ht1 += over;
            P += v2p;
            float ht3 = cPh * P;
            P -= ht3;

            // fused 15-tap gamma-UH convolution (shift register)
            float q = ht2 + ht3;
#pragma unroll
            for (int l = 14; l > 0; l--) { hs[l] = hs[l - 1]; hd[l] = hd[l - 1]; }
            hs[0] = ht0; hd[0] = ht1;
#pragma unroll
            for (int l = 0; l < 15; l++) q += uh1[l] * hs[l] + uh2[l] * hd[l];

            if (active) out[(size_t)(t0 + i) * GG + g] = q;
        }
        __syncwarp();
    }
}

extern "C" void kernel_launch(void* const* d_in, const int* in_sizes, int n_in,
                              void* d_out, int out_size)
{
    (void)in_sizes; (void)n_in; (void)out_size;
    const float* x   = (const float*)d_in[0];   // x_phy  [1460, 5000, 3]
    const float* par = (const float*)d_in[1];   // params [1460, 5000, 20]
    float* out = (float*)d_out;                 // Q      [1460, 5000]
    hmets_kernel<<<(GG + 31) / 32, 32>>>(x, par, out);
}

// round 3
// speedup vs baseline: 1.3491x; 1.3491x over previous
#include <cuda_runtime.h>
#include <math.h>

#define TT   1460
#define TT2  1470            // padded to a multiple of 15
#define GG   5000
#define TS   30              // timesteps per smem tile (2 x 15-chunk)
#define NT   49              // 1470 / 30
#define ROWF 96              // 32 cells * 3 floats per timestep row

// ---- Blackwell packed f32x2 + approx transcendental helpers -------------------
#define PACK2(d, lo, hi)   asm("mov.b64 %0, {%1, %2};" : "=l"(d) : "f"(lo), "f"(hi))
#define UNPACK2(lo, hi, d) asm("mov.b64 {%0, %1}, %2;" : "=f"(lo), "=f"(hi) : "l"(d))
#define FMA2(d, a, b, c)   asm("fma.rn.f32x2 %0, %1, %2, %3;" : "=l"(d) : "l"(a), "l"(b), "l"(c))

__device__ __forceinline__ float lg2a(float x) { float r; asm("lg2.approx.f32 %0, %1;" : "=f"(r) : "f"(x)); return r; }
__device__ __forceinline__ float ex2a(float x) { float r; asm("ex2.approx.f32 %0, %1;" : "=f"(r) : "f"(x)); return r; }

__device__ __forceinline__ void cp_async16(void* sm, const void* gm) {
    unsigned a = (unsigned)__cvta_generic_to_shared(sm);
    asm volatile("cp.async.cg.shared.global [%0], [%1], 16;\n" :: "r"(a), "l"(gm));
}
__device__ __forceinline__ void cp_commit() { asm volatile("cp.async.commit_group;\n" ::: "memory"); }
__device__ __forceinline__ void cp_wait1()  { asm volatile("cp.async.wait_group 1;\n" ::: "memory"); }
__device__ __forceinline__ void cp_wait0()  { asm volatile("cp.async.wait_group 0;\n" ::: "memory"); }

__global__ __launch_bounds__(32, 1)
void hmets_kernel(const float* __restrict__ x,
                  const float* __restrict__ par,
                  float* __restrict__ out)
{
    __shared__ float sm[2 * TS * ROWF];   // 23040 B double buffered
    const int lane = threadIdx.x;
    const int g0   = blockIdx.x * 32;
    const int g    = g0 + lane;
    const bool active  = (g < GG);
    const bool fullblk = (g0 + 32 <= GG);

    // ---------------- parameters: only the last timestep row is live ----------------
    const float* pr = par + ((size_t)(TT - 1) * GG + (active ? g : (GG - 1))) * 20;
    float s[20];
#pragma unroll
    for (int i = 0; i < 20; i++) {
        float v = __ldg(pr + i);
        s[i] = 1.0f / (1.0f + expf(-v));
    }
    const float ddf_min = 20.0f * s[0];
    const float ddf_sum = ddf_min + 20.0f * s[1];
    const float Tbm     = -2.0f + 5.0f * s[2];
    const float Kcum    = 0.01f + 0.19f * s[3];
    const float fcmin   = 0.1f * s[4];
    const float fc_sum  = fcmin + 0.01f + 0.24f * s[5];
    const float Ccum    = 0.005f + 0.045f * s[6];
    const float Tbf     = -5.0f + 7.0f * s[7];
    const float Kf      = 5.0f * s[8];
    const float efe     = s[9];
    const float ETe     = 3.0f * s[10];
    const float cRun    = s[11];
    const float cV2P    = 1e-5f + (0.02f - 1e-5f) * s[12];
    const float cVad    = 0.1f * s[13];
    const float cPh     = 1e-5f + (0.01f - 1e-5f) * s[14];
    const float Vmax    = 0.001f + (500.0f - 0.001f) * s[15];
    const float invVmax = 1.0f / Vmax;

    // ---------------- gamma unit hydrographs, packed (uh1[l], uh2[l]) ---------------
    unsigned long long uhp[15];
    {
        float a1 = 0.3f  + (20.0f - 0.3f)  * s[16];
        float b1 = 0.01f + (5.0f  - 0.01f) * s[17];
        float a2 = 0.5f  + (13.0f - 0.5f)  * s[18];
        float b2 = 0.15f + (1.5f  - 0.15f) * s[19];
        float i1 = 1.0f / b1, i2 = 1.0f / b2;
        float w1[15], w2[15];
        float n1 = 0.f, n2 = 0.f;
#pragma unroll
        for (int l = 0; l < 15; l++) {
            float t  = (float)l + 0.5f;
            w1[l] = powf(t, a1 - 1.0f) * expf(-t * i1);
            w2[l] = powf(t, a2 - 1.0f) * expf(-t * i2);
            n1 += w1[l]; n2 += w2[l];
        }
        n1 = 1.0f / n1; n2 = 1.0f / n2;
#pragma unroll
        for (int l = 0; l < 15; l++) PACK2(uhp[l], w1[l] * n1, w2[l] * n2);
    }

    // ---------------- tile prefetch (zero-fill beyond TT and for tail cells) --------
    auto prefetch = [&](int k) {
        float* dst = sm + (k & 1) * (TS * ROWF);
        int t0 = k * TS;
        if (fullblk) {
            for (int j = lane; j < TS * 24; j += 32) {       // 24 float4 per row
                int row = j / 24, c = j - row * 24;
                if (t0 + row < TT) {
                    const float* gp = x + (size_t)(t0 + row) * (GG * 3) + g0 * 3 + c * 4;
                    cp_async16(dst + row * ROWF + c * 4, gp);
                } else {
                    float4 z = {0.f, 0.f, 0.f, 0.f};
                    *(float4*)(dst + row * ROWF + c * 4) = z;
                }
            }
        } else {
            for (int j = lane; j < TS * ROWF; j += 32) {
                int row = j / ROWF, c = j - row * ROWF;
                int cell = g0 + c / 3;
                float v = (cell < GG && t0 + row < TT)
                        ? __ldg(x + (size_t)(t0 + row) * (GG * 3) + g0 * 3 + c)
                        : 0.0f;
                dst[row * ROWF + c] = v;
            }
        }
        cp_commit();
    };

    // ---------------- state + packed conv history (circular, unroll-aligned) --------
    float S = 1e-5f, W = 1e-5f, C = 1e-5f, P = 1e-5f;
    float V = 0.5f * Vmax;
    unsigned long long hpk[15];
#pragma unroll
    for (int l = 0; l < 15; l++) hpk[l] = 0ull;

    float* op = out + g;          // advances by GG per step

    prefetch(0);
    for (int k = 0; k < NT; k++) {
        const int t0 = k * TS;
        if (k + 1 < NT) { prefetch(k + 1); cp_wait1(); }
        else            { cp_wait0(); }
        __syncwarp();
        const float* sb = sm + (k & 1) * (TS * ROWF);

#pragma unroll 1
        for (int c2 = 0; c2 < 2; c2++) {        // two aligned 15-chunks per tile
            const float* rb = sb + c2 * 15 * ROWF + lane * 3;
            const int tb = t0 + c2 * 15;
#pragma unroll
            for (int u = 0; u < 15; u++) {
                float Pp = rb[u * ROWF + 0];
                float Tt = rb[u * ROWF + 1];
                float PE = rb[u * ROWF + 2];

                float rain = (Tt >= 0.0f) ? Pp : 0.0f;
                float snow = Pp - rain;

                // refreeze (MUFU path, off the state chain)
                float base   = fmaxf(Tbf - Tt, 1e-5f);
                float pot_fr = Kf * ex2a(efe * lg2a(base));
                float fr     = fminf(pot_fr, W);
                W -= fr;
                S += fr;

                // melt
                float ddf  = fminf(ddf_sum, ddf_min * fmaf(Kcum, C, 1.0f));
                float melt = fminf(fmaxf(ddf * (Tt - Tbm), 0.0f), S + snow);
                S = S + snow - melt;
                C = (S > 1e-5f) ? (C + melt) : 0.0f;

                // water retention
                float wrf  = fmaxf(fc_sum * fmaf(-Ccum, C, 1.0f), fcmin);
                float wr   = wrf * S;
                float wtmp = W + melt + rain;
                float wa   = fmaxf(wtmp - wr, 0.0f);
                W = (wa > 0.0f) ? wr : wtmp;

                // vadose / phreatic
                float RET   = ETe * PE;
                float ratio = V * invVmax;
                float ht0   = cRun * ratio * wa;
                float infil = fmaxf(wa - ht0 - RET, 0.0f);
                float ht1   = cRun * ratio * ratio * infil;
                float ht2   = cVad * V;
                float v2p   = cV2P * V;
                V = V + infil - ht1 - ht2 - v2p;
                float over = fmaxf(V - Vmax, 0.0f);
                V -= over;
                ht1 += over;
                P += v2p;
                float ht3 = cPh * P;
                P -= ht3;

                // 15-tap dual UH conv: packed FFMA2 on a register-renamed ring
                PACK2(hpk[u], ht0, ht1);
                unsigned long long qp = 0ull;
#pragma unroll
                for (int l = 0; l < 15; l++)
                    FMA2(qp, uhp[l], hpk[(u - l + 15) % 15], qp);
                float qlo, qhi;
                UNPACK2(qlo, qhi, qp);
                float q = (ht2 + ht3) + qlo + qhi;

                if (active && (tb + u) < TT) *op = q;
                op += GG;
            }
        }
        __syncwarp();
    }
}

extern "C" void kernel_launch(void* const* d_in, const int* in_sizes, int n_in,
                              void* d_out, int out_size)
{
    (void)in_sizes; (void)n_in; (void)out_size;
    const float* x   = (const float*)d_in[0];   // x_phy  [1460, 5000, 3]
    const float* par = (const float*)d_in[1];   // params [1460, 5000, 20]
    float* out = (float*)d_out;                 // Q      [1460, 5000]
    hmets_kernel<<<(GG + 31) / 32, 32>>>(x, par, out);
}